// round 5
// baseline (speedup 1.0000x reference)
#include <cuda_runtime.h>
#include <cstdint>

#define FEATURE_COUNT 106496LL
#define ACCUM 256
#define LEAK 0.1f
#define MAXB 16384
#define NSTAGE 3
#define PF 2
#define GRID_MAIN 296          // 2 blocks per SM on 148-SM B200

// ---------------------------------------------------------------------------
// device scratch (allocation-free rule: __device__ globals)
// ---------------------------------------------------------------------------
__device__ int g_is64;
__device__ int g_sorted[MAXB];   // batch ids, sorted by sel
__device__ int g_sel[MAXB];      // sel per batch

__device__ __forceinline__ long long geti(const void* p, long long i, int is64) {
    return is64 ? ((const long long*)p)[i] : (long long)((const int*)p)[i];
}

__device__ __forceinline__ float clipped_relu(float x) {
    float c = fminf(fmaxf(x, -1.0f), 127.0f / 128.0f);
    return c + LEAK * (x - c);
}

__device__ __forceinline__ uint32_t smem_u32(const void* p) {
    uint32_t a;
    asm("{ .reg .u64 t; cvta.to.shared.u64 t, %1; cvt.u32.u64 %0, t; }"
        : "=r"(a) : "l"(p));
    return a;
}

// ---------------------------------------------------------------------------
// Pre-pass: dtype detection + counting sort of batches by sel (16 buckets).
// One block. Output is written per-batch, so bucket-internal order (atomic
// order nondeterminism) cannot affect results.
// ---------------------------------------------------------------------------
__global__ void prep_kernel(const void* __restrict__ indices,
                            const void* __restrict__ which_model,
                            const void* __restrict__ lengths,
                            int B)
{
    __shared__ int s_cnt[16];
    __shared__ int s_off[16];
    __shared__ int s_is64;
    const int t = threadIdx.x;

    if (t == 0) {
        const long long* p = (const long long*)indices;
        int ok = 1;
        #pragma unroll
        for (int k = 0; k < 16; k++) {
            long long v = p[k];
            if (v < 0 || v >= FEATURE_COUNT) ok = 0;
        }
        g_is64 = ok;
        s_is64 = ok;
    }
    if (t < 16) s_cnt[t] = 0;
    __syncthreads();
    const int is64 = s_is64;

    for (int b = t; b < B; b += blockDim.x) {
        int wm = (int)geti(which_model, b, is64);
        int le = (int)geti(lengths, b, is64);
        int sel = wm + (le / 17) * 4;
        g_sel[b] = sel;
        atomicAdd(&s_cnt[sel], 1);
    }
    __syncthreads();
    if (t == 0) {
        int run = 0;
        #pragma unroll
        for (int k = 0; k < 16; k++) { s_off[k] = run; run += s_cnt[k]; }
    }
    __syncthreads();
    for (int b = t; b < B; b += blockDim.x) {
        int pos = atomicAdd(&s_off[g_sel[b]], 1);
        g_sorted[pos] = b;
    }
}

// ---------------------------------------------------------------------------
// Main kernel: persistent blocks over a contiguous chunk of the sorted batch
// list. 3-stage cp.async.bulk pipeline (depth-2 prefetch) keeps ~128KB/SM of
// bulk copies in flight continuously. Sorted sel => W1/W2 slices L1-resident.
// ---------------------------------------------------------------------------
extern __shared__ __align__(16) float s_stage[];   // NSTAGE*32*256 f32 = 96KB

__global__ __launch_bounds__(256) void nnue_main(
    const void*  __restrict__ indices,
    const void*  __restrict__ offsets,
    const float* __restrict__ embed,
    const float* __restrict__ bias,
    const float* __restrict__ W1, const float* __restrict__ b1,
    const float* __restrict__ W2, const float* __restrict__ b2,
    const float* __restrict__ W3, const float* __restrict__ b3,
    float* __restrict__ out,
    long long n_idx, int B)
{
    __shared__ __align__(8)  unsigned long long s_mbar[NSTAGE];
    __shared__ __align__(16) float s_emb[ACCUM];
    __shared__ __align__(16) float s_h1[16];
    __shared__ float s_psqt;

    const int t = threadIdx.x;
    const int is64 = g_is64;

    const int chunk = (B + (int)gridDim.x - 1) / (int)gridDim.x;
    const int beg = blockIdx.x * chunk;
    const int end = min(beg + chunk, B);
    const int n = end - beg;
    if (n <= 0) return;

    if (t == 0) {
        #pragma unroll
        for (int s = 0; s < NSTAGE; s++)
            asm volatile("mbarrier.init.shared.b64 [%0], %1;"
                         :: "r"(smem_u32(&s_mbar[s])), "r"(1) : "memory");
    }
    __syncthreads();

    const uint32_t stage_base = smem_u32(s_stage);

    // issue one batch's row copies into stage (i % NSTAGE); warp 0 only
    auto issue = [&](int i) {
        const int b = g_sorted[beg + i];
        const long long lo = geti(offsets, b, is64);
        const long long hi = (b + 1 < B) ? geti(offsets, b + 1, is64) : n_idx;
        const int st = min((int)(hi - lo), 32);
        const int s = i % NSTAGE;
        const uint32_t mbar = smem_u32(&s_mbar[s]);
        if ((t & 31) == 0)
            asm volatile("mbarrier.arrive.expect_tx.shared.b64 _, [%0], %1;"
                         :: "r"(mbar), "r"((unsigned)(st * 1024)) : "memory");
        __syncwarp();
        if (t < st) {
            long long id = geti(indices, lo + t, is64);
            const float* src = embed + id * ACCUM;
            uint32_t dst = stage_base + (uint32_t)s * 32768u + (uint32_t)t * 1024u;
            asm volatile(
                "cp.async.bulk.shared::cta.global.mbarrier::complete_tx::bytes "
                "[%0], [%1], %2, [%3];"
                :: "r"(dst), "l"(src), "r"(1024), "r"(mbar) : "memory");
        }
    };

    if (t < 32) {
        const int pro = min(PF, n);
        for (int j = 0; j < pro; j++) issue(j);
    }

    for (int i = 0; i < n; i++) {
        if (t < 32 && i + PF < n) issue(i + PF);

        // wait for stage i%NSTAGE, phase parity (i/NSTAGE)&1
        {
            const uint32_t mbar = smem_u32(&s_mbar[i % NSTAGE]);
            const int par = (i / NSTAGE) & 1;
            uint32_t done;
            asm volatile(
                "{\n\t.reg .pred p;\n\t"
                "mbarrier.try_wait.parity.acquire.cta.shared::cta.b64 p, [%1], %2;\n\t"
                "selp.b32 %0, 1, 0, p;\n\t}"
                : "=r"(done) : "r"(mbar), "r"(par) : "memory");
            while (!done)
                asm volatile(
                    "{\n\t.reg .pred p;\n\t"
                    "mbarrier.try_wait.parity.acquire.cta.shared::cta.b64 p, [%1], %2, 0x989680;\n\t"
                    "selp.b32 %0, 1, 0, p;\n\t}"
                    : "=r"(done) : "r"(mbar), "r"(par) : "memory");
        }

        const int b   = g_sorted[beg + i];
        const int sel = g_sel[b];
        const float* __restrict__ st_base = s_stage + (i % NSTAGE) * (32 * ACCUM);

        // ---- accumulate: thread t owns column t over the staged rows ----
        const long long lo = geti(offsets, b, is64);
        const long long hi = (b + 1 < B) ? geti(offsets, b + 1, is64) : n_idx;
        const int cnt = (int)(hi - lo);
        const int staged = min(cnt, 32);

        float a0 = bias[t], a1 = 0.0f;
        if (staged == 32) {
            #pragma unroll
            for (int r = 0; r < 32; r += 2) {
                a0 += st_base[r * ACCUM + t];
                a1 += st_base[(r + 1) * ACCUM + t];
            }
        } else {
            for (int r = 0; r < staged; r++) a0 += st_base[r * ACCUM + t];
        }
        for (int r = 32; r < cnt; r++) {          // safety tail (not taken: L=32)
            long long id = geti(indices, lo + r, is64);
            a0 += embed[id * ACCUM + t];
        }
        float acc = a0 + a1;

        if (t == 0) s_psqt = acc;                 // pre-activation column 0
        s_emb[t] = clipped_relu(acc);
        __syncthreads();                          // data ready; stage consumed

        // ---- layer 1: 16 outputs x 16 lanes; W1 slice L1-hot (sorted sel) ----
        {
            const int o = t >> 4;
            const int k = t & 15;
            const float4* __restrict__ w =
                (const float4*)(W1 + ((long long)sel * 16 + o) * ACCUM) + k * 4;
            const float4* __restrict__ e = (const float4*)s_emb + k * 4;
            float s = 0.0f;
            #pragma unroll
            for (int j = 0; j < 4; j++) {
                float4 wv = w[j], ev = e[j];
                s += wv.x * ev.x + wv.y * ev.y + wv.z * ev.z + wv.w * ev.w;
            }
            s += __shfl_xor_sync(0xffffffffu, s, 1);
            s += __shfl_xor_sync(0xffffffffu, s, 2);
            s += __shfl_xor_sync(0xffffffffu, s, 4);
            s += __shfl_xor_sync(0xffffffffu, s, 8);
            if (k == 0) s_h1[o] = clipped_relu(s + b1[sel * 16 + o]);
        }
        __syncthreads();

        // ---- layers 2+3 + epilogue (warp 0) ----
        if (t < 32) {
            const float4* __restrict__ w2 =
                (const float4*)(W2 + ((long long)sel * 32 + t) * 16);
            float4 h0 = ((const float4*)s_h1)[0];
            float4 h1v = ((const float4*)s_h1)[1];
            float4 h2v = ((const float4*)s_h1)[2];
            float4 h3v = ((const float4*)s_h1)[3];
            float4 wa = w2[0], wb = w2[1], wc = w2[2], wd = w2[3];
            float s = b2[sel * 32 + t]
                + wa.x * h0.x + wa.y * h0.y + wa.z * h0.z + wa.w * h0.w
                + wb.x * h1v.x + wb.y * h1v.y + wb.z * h1v.z + wb.w * h1v.w
                + wc.x * h2v.x + wc.y * h2v.y + wc.z * h2v.z + wc.w * h2v.w
                + wd.x * h3v.x + wd.y * h3v.y + wd.z * h3v.z + wd.w * h3v.w;
            float p = clipped_relu(s) * W3[sel * 32 + t];
            #pragma unroll
            for (int off = 16; off > 0; off >>= 1)
                p += __shfl_xor_sync(0xffffffffu, p, off);
            if (t == 0)
                out[b] = tanhf(p + b3[sel] + s_psqt);
        }
        // stage reuse for iteration i+NSTAGE is guarded: its issue happens at
        // iteration i+NSTAGE-PF, strictly after this iteration's first
        // __syncthreads() (all reads of the stage complete before it).
    }
}

extern "C" void kernel_launch(void* const* d_in, const int* in_sizes, int n_in,
                              void* d_out, int out_size) {
    const void*  indices     = d_in[0];
    const void*  offsets     = d_in[1];
    const void*  which_model = d_in[2];
    const void*  lengths     = d_in[3];
    const float* embed       = (const float*)d_in[4];
    const float* bias        = (const float*)d_in[5];
    const float* W1 = (const float*)d_in[6];
    const float* b1 = (const float*)d_in[7];
    const float* W2 = (const float*)d_in[8];
    const float* b2 = (const float*)d_in[9];
    const float* W3 = (const float*)d_in[10];
    const float* b3 = (const float*)d_in[11];

    long long n_idx = in_sizes[0];
    int B = in_sizes[1];
    if (B > MAXB) B = MAXB;   // problem shape is B=8192; scratch guard

    const int dyn_smem = NSTAGE * 32 * ACCUM * (int)sizeof(float);  // 96KB
    cudaFuncSetAttribute(nnue_main,
                         cudaFuncAttributeMaxDynamicSharedMemorySize,
                         dyn_smem);

    prep_kernel<<<1, 256>>>(indices, which_model, lengths, B);
    nnue_main<<<GRID_MAIN, 256, dyn_smem>>>(indices, offsets,
                                            embed, bias, W1, b1, W2, b2, W3, b3,
                                            (float*)d_out, n_idx, B);
}

// round 6
// speedup vs baseline: 1.5848x; 1.5848x over previous
#include <cuda_runtime.h>
#include <cstdint>

#define FEATURE_COUNT 106496LL
#define ACCUM 256
#define LEAK 0.1f
#define NSTAGE 3
#define PF 2
#define GRID_MAIN 296           // 2 blocks/SM on 148-SM B200
#define TMA_NUM 11              // TMA role gets n*11/28 of each chunk

__device__ __forceinline__ long long geti(const void* p, long long i, int is64) {
    return is64 ? ((const long long*)p)[i] : (long long)((const int*)p)[i];
}

__device__ __forceinline__ float clipped_relu(float x) {
    float c = fminf(fmaxf(x, -1.0f), 127.0f / 128.0f);
    return c + LEAK * (x - c);
}

__device__ __forceinline__ uint32_t smem_u32(const void* p) {
    uint32_t a;
    asm("{ .reg .u64 t; cvta.to.shared.u64 t, %1; cvt.u32.u64 %0, t; }"
        : "=r"(a) : "l"(p));
    return a;
}

#define BARX(id, cnt) asm volatile("bar.sync %0, %1;" :: "r"(id), "r"(cnt) : "memory")

__device__ __forceinline__ void mbar_wait(uint32_t mbar, int par) {
    uint32_t done;
    asm volatile(
        "{\n\t.reg .pred p;\n\t"
        "mbarrier.try_wait.parity.acquire.cta.shared::cta.b64 p, [%1], %2;\n\t"
        "selp.b32 %0, 1, 0, p;\n\t}"
        : "=r"(done) : "r"(mbar), "r"(par) : "memory");
    while (!done)
        asm volatile(
            "{\n\t.reg .pred p;\n\t"
            "mbarrier.try_wait.parity.acquire.cta.shared::cta.b64 p, [%1], %2, 0x989680;\n\t"
            "selp.b32 %0, 1, 0, p;\n\t}"
            : "=r"(done) : "r"(mbar), "r"(par) : "memory");
}

// ---------------------------------------------------------------------------
// Fused hybrid kernel. 384 threads:
//   t in [0,256): TMA role — 3-stage cp.async.bulk pipeline over the first
//                 nT batches of this block's chunk (TMA engine path).
//   t in [256,384): LDG role — two 64-thread groups, one batch each, direct
//                 LDG.128 gather with shfl-broadcast indices (L1tex path).
// The two roles saturate DIFFERENT per-SM request-rate limits concurrently.
// ---------------------------------------------------------------------------
extern __shared__ __align__(16) float s_stage[];   // NSTAGE*32*256 f32 = 96KB

__global__ __launch_bounds__(384, 2) void nnue_fused(
    const void*  __restrict__ indices,
    const void*  __restrict__ offsets,
    const void*  __restrict__ which_model,
    const void*  __restrict__ lengths,
    const float* __restrict__ embed,
    const float* __restrict__ bias,
    const float* __restrict__ W1, const float* __restrict__ b1,
    const float* __restrict__ W2, const float* __restrict__ b2,
    const float* __restrict__ W3, const float* __restrict__ b3,
    float* __restrict__ out,
    long long n_idx, int B)
{
    __shared__ __align__(8)  unsigned long long s_mbar[NSTAGE];
    __shared__ __align__(16) float  s_embT[ACCUM];
    __shared__ __align__(16) float  s_h1T[16];
    __shared__ __align__(16) float4 s_embL[2][64];
    __shared__ __align__(16) float  s_h1L[2][16];
    __shared__ float s_psqtT, s_psqtL[2];
    __shared__ int   s_is64;

    const int t = threadIdx.x;
    const int chunk = (B + (int)gridDim.x - 1) / (int)gridDim.x;
    const int beg = blockIdx.x * chunk;
    const int end = min(beg + chunk, B);
    const int n = end - beg;
    if (n <= 0) return;
    const int nT = (n * TMA_NUM) / 28;   // TMA role's share of the chunk

    // dtype detection (one warp, one ballot) + mbarrier init
    if (t < 32) {
        int ok = 1;
        if (t < 16) {
            long long v = ((const long long*)indices)[t];
            ok = (v >= 0 && v < FEATURE_COUNT);
        }
        unsigned m = __ballot_sync(0xffffffffu, ok);
        if (t == 0) {
            s_is64 = (m == 0xffffffffu) ? 1 : 0;
            #pragma unroll
            for (int s = 0; s < NSTAGE; s++)
                asm volatile("mbarrier.init.shared.b64 [%0], %1;"
                             :: "r"(smem_u32(&s_mbar[s])), "r"(1) : "memory");
        }
    }
    __syncthreads();
    const int is64 = s_is64;
    const float4* __restrict__ E4 = (const float4*)embed;

    if (t < 256) {
        // ================= TMA role: batches [beg, beg+nT) =================
        const uint32_t stage_base = smem_u32(s_stage);

        auto issue = [&](int i) {
            const int b = beg + i;
            const long long lo = geti(offsets, b, is64);
            const long long hi = (b + 1 < B) ? geti(offsets, b + 1, is64) : n_idx;
            const int st = min((int)(hi - lo), 32);
            const int s = i % NSTAGE;
            const uint32_t mbar = smem_u32(&s_mbar[s]);
            if (t == 0)
                asm volatile("mbarrier.arrive.expect_tx.shared.b64 _, [%0], %1;"
                             :: "r"(mbar), "r"((unsigned)(st * 1024)) : "memory");
            __syncwarp();
            if (t < st) {
                long long id = geti(indices, lo + t, is64);
                const float* src = embed + id * ACCUM;
                uint32_t dst = stage_base + (uint32_t)s * 32768u + (uint32_t)t * 1024u;
                asm volatile(
                    "cp.async.bulk.shared::cta.global.mbarrier::complete_tx::bytes "
                    "[%0], [%1], %2, [%3];"
                    :: "r"(dst), "l"(src), "r"(1024), "r"(mbar) : "memory");
            }
        };

        if (t < 32) {
            const int pro = min(PF, nT);
            for (int j = 0; j < pro; j++) issue(j);
        }

        for (int i = 0; i < nT; i++) {
            if (t < 32 && i + PF < nT) issue(i + PF);

            mbar_wait(smem_u32(&s_mbar[i % NSTAGE]), (i / NSTAGE) & 1);

            const int b = beg + i;
            const long long lo = geti(offsets, b, is64);
            const long long hi = (b + 1 < B) ? geti(offsets, b + 1, is64) : n_idx;
            const int cnt = (int)(hi - lo);
            const int staged = min(cnt, 32);
            const float* __restrict__ st_base = s_stage + (i % NSTAGE) * (32 * ACCUM);

            float a0 = bias[t], a1 = 0.0f;
            if (staged == 32) {
                #pragma unroll
                for (int r = 0; r < 32; r += 2) {
                    a0 += st_base[r * ACCUM + t];
                    a1 += st_base[(r + 1) * ACCUM + t];
                }
            } else {
                for (int r = 0; r < staged; r++) a0 += st_base[r * ACCUM + t];
            }
            for (int r = 32; r < cnt; r++) {      // safety tail (L=32: unused)
                long long id = geti(indices, lo + r, is64);
                a0 += embed[id * ACCUM + t];
            }
            float acc = a0 + a1;

            if (t == 0) s_psqtT = acc;            // pre-activation column 0
            s_embT[t] = clipped_relu(acc);
            BARX(3, 256);

            const int sel = (int)geti(which_model, b, is64)
                          + ((int)geti(lengths, b, is64) / 17) * 4;

            // layer 1: 16 outputs x 16 lanes
            {
                const int o = t >> 4;
                const int k = t & 15;
                const float4* __restrict__ w =
                    (const float4*)(W1 + ((long long)sel * 16 + o) * ACCUM) + k * 4;
                const float4* __restrict__ e = (const float4*)s_embT + k * 4;
                float s = 0.0f;
                #pragma unroll
                for (int j = 0; j < 4; j++) {
                    float4 wv = w[j], ev = e[j];
                    s += wv.x * ev.x + wv.y * ev.y + wv.z * ev.z + wv.w * ev.w;
                }
                s += __shfl_xor_sync(0xffffffffu, s, 1);
                s += __shfl_xor_sync(0xffffffffu, s, 2);
                s += __shfl_xor_sync(0xffffffffu, s, 4);
                s += __shfl_xor_sync(0xffffffffu, s, 8);
                if (k == 0) s_h1T[o] = clipped_relu(s + b1[sel * 16 + o]);
            }
            BARX(3, 256);

            if (t < 32) {                         // layers 2+3 + epilogue
                const float4* __restrict__ w2 =
                    (const float4*)(W2 + ((long long)sel * 32 + t) * 16);
                float4 h0 = ((const float4*)s_h1T)[0];
                float4 h1v = ((const float4*)s_h1T)[1];
                float4 h2v = ((const float4*)s_h1T)[2];
                float4 h3v = ((const float4*)s_h1T)[3];
                float4 wa = w2[0], wb = w2[1], wc = w2[2], wd = w2[3];
                float s = b2[sel * 32 + t]
                    + wa.x * h0.x + wa.y * h0.y + wa.z * h0.z + wa.w * h0.w
                    + wb.x * h1v.x + wb.y * h1v.y + wb.z * h1v.z + wb.w * h1v.w
                    + wc.x * h2v.x + wc.y * h2v.y + wc.z * h2v.z + wc.w * h2v.w
                    + wd.x * h3v.x + wd.y * h3v.y + wd.z * h3v.z + wd.w * h3v.w;
                float p = clipped_relu(s) * W3[sel * 32 + t];
                #pragma unroll
                for (int off = 16; off > 0; off >>= 1)
                    p += __shfl_xor_sync(0xffffffffu, p, off);
                if (t == 0) out[b] = tanhf(p + b3[sel] + s_psqtT);
            }
        }
    } else {
        // ============ LDG role: batches [beg+nT, end), 2 groups ============
        const int gt   = t - 256;      // 0..127
        const int grp  = gt >> 6;      // 0 or 1
        const int lane = gt & 63;      // lane within the 64-thread group
        const int wl   = gt & 31;      // lane within warp
        const int barid = 1 + grp;

        for (int b = beg + nT + grp; b < end; b += 2) {
            const long long lo = geti(offsets, b, is64);
            const long long hi = (b + 1 < B) ? geti(offsets, b + 1, is64) : n_idx;
            const int cnt = (int)(hi - lo);
            const int pre = min(cnt, 32);

            // preload indices: each warp holds all 32 ids in registers
            int myid = 0;
            if (wl < pre) myid = (int)geti(indices, lo + wl, is64);

            float4 acc = ((const float4*)bias)[lane];
            if (pre == 32) {
                #pragma unroll 8
                for (int r = 0; r < 32; r++) {
                    int id = __shfl_sync(0xffffffffu, myid, r);
                    float4 v = E4[(long long)id * 64 + lane];
                    acc.x += v.x; acc.y += v.y; acc.z += v.z; acc.w += v.w;
                }
            } else {
                for (int r = 0; r < pre; r++) {
                    int id = __shfl_sync(0xffffffffu, myid, r);
                    float4 v = E4[(long long)id * 64 + lane];
                    acc.x += v.x; acc.y += v.y; acc.z += v.z; acc.w += v.w;
                }
            }
            for (long long j = lo + 32; j < hi; j++) {   // safety tail
                float4 v = E4[geti(indices, j, is64) * 64 + lane];
                acc.x += v.x; acc.y += v.y; acc.z += v.z; acc.w += v.w;
            }

            if (lane == 0) s_psqtL[grp] = acc.x;  // pre-activation column 0
            s_embL[grp][lane] = make_float4(clipped_relu(acc.x), clipped_relu(acc.y),
                                            clipped_relu(acc.z), clipped_relu(acc.w));
            BARX(barid, 64);

            const int sel = (int)geti(which_model, b, is64)
                          + ((int)geti(lengths, b, is64) / 17) * 4;

            // layer 1: 16 outputs x 4 lanes (shuffle partners share a warp)
            {
                const int o = lane >> 2;
                const int k = lane & 3;
                const float4* __restrict__ w =
                    (const float4*)(W1 + ((long long)sel * 16 + o) * ACCUM) + k * 16;
                const float4* __restrict__ e = &s_embL[grp][0] + k * 16;
                float s = 0.0f;
                #pragma unroll
                for (int j = 0; j < 16; j++) {
                    float4 wv = w[j], ev = e[j];
                    s += wv.x * ev.x + wv.y * ev.y + wv.z * ev.z + wv.w * ev.w;
                }
                s += __shfl_xor_sync(0xffffffffu, s, 1);
                s += __shfl_xor_sync(0xffffffffu, s, 2);
                if (k == 0) s_h1L[grp][o] = clipped_relu(s + b1[sel * 16 + o]);
            }
            BARX(barid, 64);

            if (lane < 32) {                      // layers 2+3 + epilogue
                const float4* __restrict__ w2 =
                    (const float4*)(W2 + ((long long)sel * 32 + lane) * 16);
                float4 h0 = ((const float4*)s_h1L[grp])[0];
                float4 h1v = ((const float4*)s_h1L[grp])[1];
                float4 h2v = ((const float4*)s_h1L[grp])[2];
                float4 h3v = ((const float4*)s_h1L[grp])[3];
                float4 wa = w2[0], wb = w2[1], wc = w2[2], wd = w2[3];
                float s = b2[sel * 32 + lane]
                    + wa.x * h0.x + wa.y * h0.y + wa.z * h0.z + wa.w * h0.w
                    + wb.x * h1v.x + wb.y * h1v.y + wb.z * h1v.z + wb.w * h1v.w
                    + wc.x * h2v.x + wc.y * h2v.y + wc.z * h2v.z + wc.w * h2v.w
                    + wd.x * h3v.x + wd.y * h3v.y + wd.z * h3v.z + wd.w * h3v.w;
                float p = clipped_relu(s) * W3[sel * 32 + lane];
                #pragma unroll
                for (int off = 16; off > 0; off >>= 1)
                    p += __shfl_xor_sync(0xffffffffu, p, off);
                if (lane == 0) out[b] = tanhf(p + b3[sel] + s_psqtL[grp]);
            }
            // no trailing bar needed: warp B can only reach its next layer-1
            // (the next s_h1L write) after the next BARX, which warp A joins
            // only after finishing layers 2+3 here.
        }
    }
}

extern "C" void kernel_launch(void* const* d_in, const int* in_sizes, int n_in,
                              void* d_out, int out_size) {
    const void*  indices     = d_in[0];
    const void*  offsets     = d_in[1];
    const void*  which_model = d_in[2];
    const void*  lengths     = d_in[3];
    const float* embed       = (const float*)d_in[4];
    const float* bias        = (const float*)d_in[5];
    const float* W1 = (const float*)d_in[6];
    const float* b1 = (const float*)d_in[7];
    const float* W2 = (const float*)d_in[8];
    const float* b2 = (const float*)d_in[9];
    const float* W3 = (const float*)d_in[10];
    const float* b3 = (const float*)d_in[11];

    long long n_idx = in_sizes[0];
    int B = in_sizes[1];

    const int dyn_smem = NSTAGE * 32 * ACCUM * (int)sizeof(float);  // 96KB
    cudaFuncSetAttribute(nnue_fused,
                         cudaFuncAttributeMaxDynamicSharedMemorySize,
                         dyn_smem);

    nnue_fused<<<GRID_MAIN, 384, dyn_smem>>>(indices, offsets, which_model,
                                             lengths, embed, bias,
                                             W1, b1, W2, b2, W3, b3,
                                             (float*)d_out, n_idx, B);
}